// round 11
// baseline (speedup 1.0000x reference)
#include <cuda_runtime.h>
#include <cuda_bf16.h>
#include <math.h>
#include <stdint.h>

#define NB   8192
#define NA   32
#define NOBS 128
#define NH1  128
#define NHX  64
#define NACT 16

// Padded bf16 row: 128 k-elements padded to 136 (272 bytes) -> lane-conflict-free
#define KPAD   136
#define ROWB   272          // bytes per row
#define ROW8B  2176         // 8 rows
#define ROW16B 4352         // 16 rows

// ---------------------------------------------------------------------------
// Scratch + prepped weight images (allocation-free rule: __device__ globals)
// ---------------------------------------------------------------------------
__device__ float g_h[NB * NA * NHX];      // 64 MB
__device__ float g_comm[NB * NA * NHX];   // 64 MB
__device__ float g_maskn[NA * NA];
// Transposed hi/lo bf16 weight images, pad-136 rows: [agent][hi|lo][n][KPAD]
__device__ unsigned char g_W1t[NA * 2 * NH1 * ROWB];   // 69632 B / agent
__device__ unsigned char g_W2t[NA * 2 * NHX * ROWB];   // 34816 B / agent
__device__ unsigned char g_Wct[NA * 2 * NHX * ROWB];   // 34816 B / agent

// ---------------------------------------------------------------------------
// Helpers
// ---------------------------------------------------------------------------
__device__ __forceinline__ uint32_t smem_u32(const void* p) {
    uint32_t a;
    asm("{ .reg .u64 t; cvta.to.shared.u64 t, %1; cvt.u32.u64 %0, t; }"
        : "=r"(a) : "l"(p));
    return a;
}
__device__ __forceinline__ uint32_t lds_u32(uint32_t addr) {
    uint32_t v; asm volatile("ld.shared.b32 %0, [%1];" : "=r"(v) : "r"(addr)); return v;
}
__device__ __forceinline__ void sts_u32(uint32_t addr, uint32_t v) {
    asm volatile("st.shared.b32 [%0], %1;" :: "r"(addr), "r"(v));
}
__device__ __forceinline__ void sts_v2(uint32_t addr, uint32_t a, uint32_t b) {
    asm volatile("st.shared.v2.b32 [%0], {%1,%2};" :: "r"(addr), "r"(a), "r"(b));
}
// d += a * b  (bf16 MMA, fp32 accumulate)
__device__ __forceinline__ void mma16816(float d[4], const uint32_t a[4], const uint32_t b[2]) {
    asm volatile(
        "mma.sync.aligned.m16n8k16.row.col.f32.bf16.bf16.f32 "
        "{%0,%1,%2,%3}, {%4,%5,%6,%7}, {%8,%9}, {%0,%1,%2,%3};"
        : "+f"(d[0]), "+f"(d[1]), "+f"(d[2]), "+f"(d[3])
        : "r"(a[0]), "r"(a[1]), "r"(a[2]), "r"(a[3]), "r"(b[0]), "r"(b[1]));
}
__device__ __forceinline__ void split_pair(float f0, float f1, uint32_t &hi, uint32_t &lo) {
    __nv_bfloat16 h0 = __float2bfloat16_rn(f0);
    __nv_bfloat16 h1 = __float2bfloat16_rn(f1);
    float l0 = f0 - __bfloat162float(h0);
    float l1 = f1 - __bfloat162float(h1);
    hi = ((uint32_t)__bfloat16_as_ushort(h1) << 16) | (uint32_t)__bfloat16_as_ushort(h0);
    lo = ((uint32_t)__bfloat16_as_ushort(__float2bfloat16_rn(l1)) << 16)
       | (uint32_t)__bfloat16_as_ushort(__float2bfloat16_rn(l0));
}

// Warp-level bf16x3 GEMM: acc[MT][NT][4] += sum of 3 split-term products.
// A tiles at rows m0.., B tiles at rows n0.., K = K16*16, pad-136 layout.
template<int MT, int NT, int K16>
__device__ __forceinline__ void warp_mma_bf16x3(
    float (&acc)[MT][NT][4],
    uint32_t sAh, uint32_t sAl, uint32_t sBh, uint32_t sBl,
    int m0, int n0, int lane)
{
    const uint32_t laneOff = (uint32_t)((lane >> 2) * ROWB + (lane & 3) * 4);
#pragma unroll
    for (int t = 0; t < 3; t++) {
        const uint32_t sa = (t == 2) ? sAl : sAh;
        const uint32_t sb = (t == 1) ? sBl : sBh;
#pragma unroll
        for (int ks = 0; ks < K16; ks++) {
            uint32_t af[MT][4];
#pragma unroll
            for (int mi = 0; mi < MT; mi++) {
                uint32_t ab = sa + (uint32_t)(m0 + mi * 16) * ROWB + (uint32_t)ks * 32 + laneOff;
                af[mi][0] = lds_u32(ab);
                af[mi][1] = lds_u32(ab + ROW8B);
                af[mi][2] = lds_u32(ab + 16);
                af[mi][3] = lds_u32(ab + ROW8B + 16);
            }
#pragma unroll
            for (int ni = 0; ni < NT; ni++) {
                uint32_t bb = sb + (uint32_t)(n0 + ni * 8) * ROWB + (uint32_t)ks * 32 + laneOff;
                uint32_t bf[2];
                bf[0] = lds_u32(bb);
                bf[1] = lds_u32(bb + 16);
#pragma unroll
                for (int mi = 0; mi < MT; mi++)
                    mma16816(acc[mi][ni], af[mi], bf);
            }
        }
    }
}

// ---------------------------------------------------------------------------
// k_mask: normalized communication matrix
// ---------------------------------------------------------------------------
__global__ void k_mask(const int* __restrict__ cm) {
    int i = threadIdx.x;
    if (i >= NA) return;
    int cnt = 0;
#pragma unroll
    for (int j = 0; j < NA; j++)
        cnt += (j != i && cm[i * NA + j] != 0) ? 1 : 0;
    float inv = 1.0f / (float)(cnt > 0 ? cnt : 1);
#pragma unroll
    for (int j = 0; j < NA; j++)
        g_maskn[i * NA + j] = (j != i && cm[i * NA + j] != 0) ? inv : 0.0f;
}

// ---------------------------------------------------------------------------
// k_prep: W -> transposed hi/lo bf16 images B[n][k] = W[k][n], pad-136 rows
// ---------------------------------------------------------------------------
__global__ void k_prep(const float* __restrict__ W1,
                       const float* __restrict__ W2,
                       const float* __restrict__ Wc) {
    const int T1 = NA * NH1 * 64;   // W1 k-pairs
    const int T2 = NA * NHX * 64;   // W2 / Wc k-pairs
    const int total = T1 + 2 * T2;
    for (int idx = blockIdx.x * blockDim.x + threadIdx.x; idx < total;
         idx += gridDim.x * blockDim.x) {
        const float* src; unsigned char* dst; int N; int t;
        if (idx < T1)           { t = idx;            src = W1; dst = g_W1t; N = NH1; }
        else if (idx < T1 + T2) { t = idx - T1;       src = W2; dst = g_W2t; N = NHX; }
        else                    { t = idx - T1 - T2;  src = Wc; dst = g_Wct; N = NHX; }
        int perA = N * 64;
        int a = t / perA, r = t % perA;
        int n = r / 64,   j = r % 64;          // j = k-pair index, k = 2j
        float f0 = src[((size_t)a * 128 + 2 * j)     * N + n];
        float f1 = src[((size_t)a * 128 + 2 * j + 1) * N + n];
        uint32_t hi, lo;
        split_pair(f0, f1, hi, lo);
        size_t half = (size_t)N * ROWB;
        unsigned char* base = dst + (size_t)a * 2 * half;
        *(uint32_t*)(base + (size_t)n * ROWB + j * 4)        = hi;
        *(uint32_t*)(base + half + (size_t)n * ROWB + j * 4) = lo;
    }
}

// ---------------------------------------------------------------------------
// k_encode: h = relu(relu(obs@W1+b1)@W2+b2) via bf16x3 mma.sync
// Block: 256 threads (8 warps), M=128 batch rows, one agent.
// smem: Ah|Al (obs, then x) 2x34816 | W1h|W1l 2x34816 | W2h|W2l 2x17408 | b1,b2
// ---------------------------------------------------------------------------
#define E_AH   0
#define E_AL   34816
#define E_W1H  69632
#define E_W1L  104448
#define E_W2H  139264
#define E_W2L  156672
#define E_B1   174080
#define E_B2   174592
#define E_SMEM 174848

__global__ __launch_bounds__(256) void k_encode(
    const float* __restrict__ obs,
    const float* __restrict__ b1, const float* __restrict__ b2)
{
    extern __shared__ unsigned char smraw[];
    const uint32_t sb = smem_u32(smraw);
    const int tid  = threadIdx.x;
    const int w    = tid >> 5;
    const int lane = tid & 31;
    const int a    = blockIdx.y;
    const int b0   = blockIdx.x * 128;

    // Stage weights (linear copies of prepped images)
    {
        const float4* s1 = (const float4*)(g_W1t + (size_t)a * 69632);
        float4* d1 = (float4*)(smraw + E_W1H);
        for (int i = tid; i < 4352; i += 256) d1[i] = s1[i];
        const float4* s2 = (const float4*)(g_W2t + (size_t)a * 34816);
        float4* d2 = (float4*)(smraw + E_W2H);
        for (int i = tid; i < 2176; i += 256) d2[i] = s2[i];
    }
    // Stage obs split hi/lo into A region
    for (int i = tid; i < 128 * 32; i += 256) {
        int m = i >> 5, kq = i & 31;                 // kq = 4-float chunk
        float4 v = *(const float4*)(obs + ((size_t)(b0 + m) * NA + a) * NOBS + kq * 4);
        uint32_t h0, l0, h1, l1;
        split_pair(v.x, v.y, h0, l0);
        split_pair(v.z, v.w, h1, l1);
        uint32_t off = (uint32_t)m * ROWB + (uint32_t)kq * 8;
        sts_v2(sb + E_AH + off, h0, h1);
        sts_v2(sb + E_AL + off, l0, l1);
    }
    if (tid < NH1) ((float*)(smraw + E_B1))[tid] = b1[a * NH1 + tid];
    if (tid < NHX) ((float*)(smraw + E_B2))[tid] = b2[a * NHX + tid];
    __syncthreads();

    // GEMM1: x[128,128] = obs @ W1 ; warp tile 64m x 32n
    {
        const int m0 = (w & 1) * 64;
        const int n0 = (w >> 1) * 32;
        float acc[4][4][4];
#pragma unroll
        for (int mi = 0; mi < 4; mi++)
#pragma unroll
            for (int ni = 0; ni < 4; ni++)
#pragma unroll
                for (int e = 0; e < 4; e++) acc[mi][ni][e] = 0.0f;

        warp_mma_bf16x3<4, 4, 8>(acc, sb + E_AH, sb + E_AL, sb + E_W1H, sb + E_W1L,
                                 m0, n0, lane);
        __syncthreads();   // everyone done reading obs tiles

        // Epilogue1: x = relu(acc + b1) -> split back into A region
        const float* b1s = (const float*)(smraw + E_B1);
#pragma unroll
        for (int mi = 0; mi < 4; mi++)
#pragma unroll
            for (int ni = 0; ni < 4; ni++) {
                int r = m0 + mi * 16 + (lane >> 2);
                int c = n0 + ni * 8 + 2 * (lane & 3);
                float bb0 = b1s[c], bb1 = b1s[c + 1];
                uint32_t hi, lo;
                float v0 = fmaxf(acc[mi][ni][0] + bb0, 0.0f);
                float v1 = fmaxf(acc[mi][ni][1] + bb1, 0.0f);
                split_pair(v0, v1, hi, lo);
                uint32_t off = (uint32_t)r * ROWB + (uint32_t)c * 2;
                sts_u32(sb + E_AH + off, hi);
                sts_u32(sb + E_AL + off, lo);
                float v2 = fmaxf(acc[mi][ni][2] + bb0, 0.0f);
                float v3 = fmaxf(acc[mi][ni][3] + bb1, 0.0f);
                split_pair(v2, v3, hi, lo);
                off += 8 * ROWB;
                sts_u32(sb + E_AH + off, hi);
                sts_u32(sb + E_AL + off, lo);
            }
    }
    __syncthreads();

    // GEMM2: h[128,64] = x @ W2 ; warp tile 32m x 32n
    {
        const int m0 = (w & 3) * 32;
        const int n0 = (w >> 2) * 32;
        float acc[2][4][4];
#pragma unroll
        for (int mi = 0; mi < 2; mi++)
#pragma unroll
            for (int ni = 0; ni < 4; ni++)
#pragma unroll
                for (int e = 0; e < 4; e++) acc[mi][ni][e] = 0.0f;

        warp_mma_bf16x3<2, 4, 8>(acc, sb + E_AH, sb + E_AL, sb + E_W2H, sb + E_W2L,
                                 m0, n0, lane);

        // Epilogue2: h = relu(acc + b2) -> g_h (float2 stores)
        const float* b2s = (const float*)(smraw + E_B2);
#pragma unroll
        for (int mi = 0; mi < 2; mi++)
#pragma unroll
            for (int ni = 0; ni < 4; ni++) {
                int r = m0 + mi * 16 + (lane >> 2);
                int c = n0 + ni * 8 + 2 * (lane & 3);
                float bb0 = b2s[c], bb1 = b2s[c + 1];
                float2 v01 = make_float2(fmaxf(acc[mi][ni][0] + bb0, 0.0f),
                                         fmaxf(acc[mi][ni][1] + bb1, 0.0f));
                float2 v23 = make_float2(fmaxf(acc[mi][ni][2] + bb0, 0.0f),
                                         fmaxf(acc[mi][ni][3] + bb1, 0.0f));
                *(float2*)(g_h + ((size_t)(b0 + r) * NA + a) * NHX + c)       = v01;
                *(float2*)(g_h + ((size_t)(b0 + r + 8) * NA + a) * NHX + c)   = v23;
            }
    }
}

// ---------------------------------------------------------------------------
// k_comm: comm[b,i,:] = sum_j M[i,j] * h[b,j,:]
// ---------------------------------------------------------------------------
__global__ __launch_bounds__(256) void k_comm() {
    __shared__ float hs[NA * NHX];
    const int tid = threadIdx.x;
    const int b = blockIdx.x;
    {
        const float4* src = (const float4*)(g_h + (size_t)b * NA * NHX);
        float4* dst = (float4*)hs;
#pragma unroll
        for (int i = tid; i < NA * NHX / 4; i += 256) dst[i] = src[i];
    }
    __syncthreads();

    const int lane = tid & 31;
    const int i0   = (tid >> 5) * 4;

    float mreg[4];
#pragma unroll
    for (int ii = 0; ii < 4; ii++) mreg[ii] = g_maskn[(i0 + ii) * NA + lane];

    float acc[4][2];
#pragma unroll
    for (int ii = 0; ii < 4; ii++) { acc[ii][0] = 0.0f; acc[ii][1] = 0.0f; }

#pragma unroll
    for (int j = 0; j < NA; j++) {
        float h0 = hs[j * NHX + lane * 2];
        float h1 = hs[j * NHX + lane * 2 + 1];
#pragma unroll
        for (int ii = 0; ii < 4; ii++) {
            float mj = __shfl_sync(0xffffffffu, mreg[ii], j);
            acc[ii][0] += mj * h0;
            acc[ii][1] += mj * h1;
        }
    }
#pragma unroll
    for (int ii = 0; ii < 4; ii++)
        *(float2*)(g_comm + ((size_t)b * NA + i0 + ii) * NHX + lane * 2) =
            make_float2(acc[ii][0], acc[ii][1]);
}

// ---------------------------------------------------------------------------
// k_final: h2 = tanh([h,comm]@Wc + bc);  q = h2@Wd + bd
// smem: Ah|Al 2x34816 (h2s overlays Ah) | Wch|Wcl 2x17408 | Wd 4096 | bc,bd
// ---------------------------------------------------------------------------
#define F_AH   0
#define F_AL   34816
#define F_WCH  69632
#define F_WCL  87040
#define F_WD   104448
#define F_BC   108544
#define F_BD   108800
#define F_SMEM 108864
#define H2S    66      // h2s fp32 row stride

__global__ __launch_bounds__(256, 2) void k_final(
    const float* __restrict__ bc, const float* __restrict__ Wd,
    const float* __restrict__ bd, float* __restrict__ q)
{
    extern __shared__ unsigned char smraw[];
    const uint32_t sbm = smem_u32(smraw);
    const int tid  = threadIdx.x;
    const int w    = tid >> 5;
    const int lane = tid & 31;
    const int a    = blockIdx.y;
    const int b0   = blockIdx.x * 128;

    // Stage Wc image, Wd, biases
    {
        const float4* s3 = (const float4*)(g_Wct + (size_t)a * 34816);
        float4* d3 = (float4*)(smraw + F_WCH);
        for (int i = tid; i < 2176; i += 256) d3[i] = s3[i];
        const float4* sw = (const float4*)(Wd + (size_t)a * NHX * NACT);
        float4* dw = (float4*)(smraw + F_WD);
        for (int i = tid; i < 256; i += 256) dw[i] = sw[i];
    }
    // Stage concat [h | comm] split hi/lo: k 0..63 = h, 64..127 = comm
    for (int i = tid; i < 128 * 32; i += 256) {
        int m = i >> 5, cchunk = i & 31;
        const float* src; int k0;
        if (cchunk < 16) { src = g_h;    k0 = cchunk * 4; }
        else             { src = g_comm; k0 = 64 + (cchunk - 16) * 4; }
        float4 v = *(const float4*)(src + ((size_t)(b0 + m) * NA + a) * NHX + (k0 & 63));
        uint32_t h0, l0, h1, l1;
        split_pair(v.x, v.y, h0, l0);
        split_pair(v.z, v.w, h1, l1);
        uint32_t off = (uint32_t)m * ROWB + (uint32_t)k0 * 2;
        sts_v2(sbm + F_AH + off, h0, h1);
        sts_v2(sbm + F_AL + off, l0, l1);
    }
    if (tid < NHX)  ((float*)(smraw + F_BC))[tid] = bc[a * NHX + tid];
    if (tid < NACT) ((float*)(smraw + F_BD))[tid] = bd[a * NACT + tid];
    __syncthreads();

    // GEMM3: pre[128,64] = concat @ Wc ; warp tile 32m x 32n
    float acc[2][4][4];
#pragma unroll
    for (int mi = 0; mi < 2; mi++)
#pragma unroll
        for (int ni = 0; ni < 4; ni++)
#pragma unroll
            for (int e = 0; e < 4; e++) acc[mi][ni][e] = 0.0f;

    const int m0 = (w & 3) * 32;
    const int n0 = (w >> 2) * 32;
    warp_mma_bf16x3<2, 4, 8>(acc, sbm + F_AH, sbm + F_AL, sbm + F_WCH, sbm + F_WCL,
                             m0, n0, lane);
    __syncthreads();   // all warps done reading A tiles before h2s overlay

    // Epilogue3: h2 = tanh(acc + bc) -> h2s fp32 [128][66] (overlays A region)
    {
        const float* bcs = (const float*)(smraw + F_BC);
        float* h2s = (float*)(smraw + F_AH);
#pragma unroll
        for (int mi = 0; mi < 2; mi++)
#pragma unroll
            for (int ni = 0; ni < 4; ni++) {
                int r = m0 + mi * 16 + (lane >> 2);
                int c = n0 + ni * 8 + 2 * (lane & 3);
                float bb0 = bcs[c], bb1 = bcs[c + 1];
                *(float2*)(h2s + r * H2S + c) =
                    make_float2(tanhf(acc[mi][ni][0] + bb0), tanhf(acc[mi][ni][1] + bb1));
                *(float2*)(h2s + (r + 8) * H2S + c) =
                    make_float2(tanhf(acc[mi][ni][2] + bb0), tanhf(acc[mi][ni][3] + bb1));
            }
    }
    __syncthreads();

    // GEMM4 (scalar): q[m, g*8..g*8+7] = h2[m,:] @ Wd + bd
    {
        const float* h2s = (const float*)(smraw + F_AH);
        const float* wds = (const float*)(smraw + F_WD);
        const float* bds = (const float*)(smraw + F_BD);
        const int m = tid & 127;
        const int g = tid >> 7;
        float accq[8];
#pragma unroll
        for (int j = 0; j < 8; j++) accq[j] = bds[g * 8 + j];
        const float* h2r = h2s + m * H2S;
#pragma unroll 4
        for (int k = 0; k < NHX; k++) {
            float av = h2r[k];
            float4 w0 = *(const float4*)(wds + k * NACT + g * 8);
            float4 w1 = *(const float4*)(wds + k * NACT + g * 8 + 4);
            accq[0] += av * w0.x; accq[1] += av * w0.y;
            accq[2] += av * w0.z; accq[3] += av * w0.w;
            accq[4] += av * w1.x; accq[5] += av * w1.y;
            accq[6] += av * w1.z; accq[7] += av * w1.w;
        }
        float* qrow = q + ((size_t)(b0 + m) * NA + a) * NACT + g * 8;
        *(float4*)qrow       = make_float4(accq[0], accq[1], accq[2], accq[3]);
        *(float4*)(qrow + 4) = make_float4(accq[4], accq[5], accq[6], accq[7]);
    }
}

// ---------------------------------------------------------------------------
extern "C" void kernel_launch(void* const* d_in, const int* in_sizes, int n_in,
                              void* d_out, int out_size) {
    const float* obs = (const float*)d_in[0];
    const float* W1  = (const float*)d_in[1];
    const float* b1  = (const float*)d_in[2];
    const float* W2  = (const float*)d_in[3];
    const float* b2  = (const float*)d_in[4];
    // d_in[5], d_in[6]: Wg, bg — dead code (gates never reach the output)
    const float* Wc  = (const float*)d_in[7];
    const float* bc  = (const float*)d_in[8];
    const float* Wd  = (const float*)d_in[9];
    const float* bd  = (const float*)d_in[10];
    const int*   cm  = (const int*)d_in[11];
    float* q = (float*)d_out;

    cudaFuncSetAttribute(k_encode, cudaFuncAttributeMaxDynamicSharedMemorySize, E_SMEM);
    cudaFuncSetAttribute(k_final,  cudaFuncAttributeMaxDynamicSharedMemorySize, F_SMEM);

    k_mask<<<1, 32>>>(cm);
    k_prep<<<256, 256>>>(W1, W2, Wc);
    k_encode<<<dim3(NB / 128, NA), 256, E_SMEM>>>(obs, b1, b2);
    k_comm<<<NB, 256>>>();
    k_final<<<dim3(NB / 128, NA), 256, F_SMEM>>>(bc, Wd, bd, q);
}

// round 12
// speedup vs baseline: 1.3857x; 1.3857x over previous
#include <cuda_runtime.h>
#include <cuda_bf16.h>
#include <math.h>
#include <stdint.h>

#define NB   8192
#define NA   32
#define NOBS 128
#define NH1  128
#define NHX  64
#define NACT 16

// Padded bf16 row: 128 k-elements padded to 136 (272 bytes) -> lane-conflict-free
#define KPAD   136
#define ROWB   272          // bytes per row
#define ROW8B  2176         // 8 rows
#define ROW16B 4352         // 16 rows

// ---------------------------------------------------------------------------
// Scratch + prepped weight images (allocation-free rule: __device__ globals)
// ---------------------------------------------------------------------------
__device__ float g_h[NB * NA * NHX];      // 64 MB
__device__ float g_comm[NB * NA * NHX];   // 64 MB
__device__ float g_maskn[NA * NA];
// Transposed hi/lo bf16 weight images, pad-136 rows: [agent][hi|lo][n][KPAD]
__device__ unsigned char g_W1t[NA * 2 * NH1 * ROWB];   // 69632 B / agent
__device__ unsigned char g_W2t[NA * 2 * NHX * ROWB];   // 34816 B / agent
__device__ unsigned char g_Wct[NA * 2 * NHX * ROWB];   // 34816 B / agent

// ---------------------------------------------------------------------------
// Helpers
// ---------------------------------------------------------------------------
__device__ __forceinline__ uint32_t smem_u32(const void* p) {
    uint32_t a;
    asm("{ .reg .u64 t; cvta.to.shared.u64 t, %1; cvt.u32.u64 %0, t; }"
        : "=r"(a) : "l"(p));
    return a;
}
__device__ __forceinline__ uint32_t lds_u32(uint32_t addr) {
    uint32_t v; asm volatile("ld.shared.b32 %0, [%1];" : "=r"(v) : "r"(addr)); return v;
}
__device__ __forceinline__ void sts_u32(uint32_t addr, uint32_t v) {
    asm volatile("st.shared.b32 [%0], %1;" :: "r"(addr), "r"(v));
}
__device__ __forceinline__ void sts_v2(uint32_t addr, uint32_t a, uint32_t b) {
    asm volatile("st.shared.v2.b32 [%0], {%1,%2};" :: "r"(addr), "r"(a), "r"(b));
}
// d += a * b  (bf16 MMA, fp32 accumulate)
__device__ __forceinline__ void mma16816(float d[4], const uint32_t a[4], const uint32_t b[2]) {
    asm volatile(
        "mma.sync.aligned.m16n8k16.row.col.f32.bf16.bf16.f32 "
        "{%0,%1,%2,%3}, {%4,%5,%6,%7}, {%8,%9}, {%0,%1,%2,%3};"
        : "+f"(d[0]), "+f"(d[1]), "+f"(d[2]), "+f"(d[3])
        : "r"(a[0]), "r"(a[1]), "r"(a[2]), "r"(a[3]), "r"(b[0]), "r"(b[1]));
}
__device__ __forceinline__ void split_pair(float f0, float f1, uint32_t &hi, uint32_t &lo) {
    __nv_bfloat16 h0 = __float2bfloat16_rn(f0);
    __nv_bfloat16 h1 = __float2bfloat16_rn(f1);
    float l0 = f0 - __bfloat162float(h0);
    float l1 = f1 - __bfloat162float(h1);
    hi = ((uint32_t)__bfloat16_as_ushort(h1) << 16) | (uint32_t)__bfloat16_as_ushort(h0);
    lo = ((uint32_t)__bfloat16_as_ushort(__float2bfloat16_rn(l1)) << 16)
       | (uint32_t)__bfloat16_as_ushort(__float2bfloat16_rn(l0));
}

// Warp-level bf16x3 GEMM: acc[MT][NT][4] += sum of 3 split-term products.
// A tiles at rows m0.., B tiles at rows n0.., K = K16*16, pad-136 layout.
template<int MT, int NT, int K16>
__device__ __forceinline__ void warp_mma_bf16x3(
    float (&acc)[MT][NT][4],
    uint32_t sAh, uint32_t sAl, uint32_t sBh, uint32_t sBl,
    int m0, int n0, int lane)
{
    const uint32_t laneOff = (uint32_t)((lane >> 2) * ROWB + (lane & 3) * 4);
#pragma unroll
    for (int t = 0; t < 3; t++) {
        const uint32_t sa = (t == 2) ? sAl : sAh;
        const uint32_t sb = (t == 1) ? sBl : sBh;
#pragma unroll
        for (int ks = 0; ks < K16; ks++) {
            uint32_t af[MT][4];
#pragma unroll
            for (int mi = 0; mi < MT; mi++) {
                uint32_t ab = sa + (uint32_t)(m0 + mi * 16) * ROWB + (uint32_t)ks * 32 + laneOff;
                af[mi][0] = lds_u32(ab);
                af[mi][1] = lds_u32(ab + ROW8B);
                af[mi][2] = lds_u32(ab + 16);
                af[mi][3] = lds_u32(ab + ROW8B + 16);
            }
#pragma unroll
            for (int ni = 0; ni < NT; ni++) {
                uint32_t bb = sb + (uint32_t)(n0 + ni * 8) * ROWB + (uint32_t)ks * 32 + laneOff;
                uint32_t bf[2];
                bf[0] = lds_u32(bb);
                bf[1] = lds_u32(bb + 16);
#pragma unroll
                for (int mi = 0; mi < MT; mi++)
                    mma16816(acc[mi][ni], af[mi], bf);
            }
        }
    }
}

// ---------------------------------------------------------------------------
// k_mask: normalized communication matrix
// ---------------------------------------------------------------------------
__global__ void k_mask(const int* __restrict__ cm) {
    int i = threadIdx.x;
    if (i >= NA) return;
    int cnt = 0;
#pragma unroll
    for (int j = 0; j < NA; j++)
        cnt += (j != i && cm[i * NA + j] != 0) ? 1 : 0;
    float inv = 1.0f / (float)(cnt > 0 ? cnt : 1);
#pragma unroll
    for (int j = 0; j < NA; j++)
        g_maskn[i * NA + j] = (j != i && cm[i * NA + j] != 0) ? inv : 0.0f;
}

// ---------------------------------------------------------------------------
// k_prep: W -> transposed hi/lo bf16 images B[n][k] = W[k][n], pad-136 rows
// ---------------------------------------------------------------------------
__global__ void k_prep(const float* __restrict__ W1,
                       const float* __restrict__ W2,
                       const float* __restrict__ Wc) {
    const int T1 = NA * NH1 * 64;   // W1 k-pairs
    const int T2 = NA * NHX * 64;   // W2 / Wc k-pairs
    const int total = T1 + 2 * T2;
    for (int idx = blockIdx.x * blockDim.x + threadIdx.x; idx < total;
         idx += gridDim.x * blockDim.x) {
        const float* src; unsigned char* dst; int N; int t;
        if (idx < T1)           { t = idx;            src = W1; dst = g_W1t; N = NH1; }
        else if (idx < T1 + T2) { t = idx - T1;       src = W2; dst = g_W2t; N = NHX; }
        else                    { t = idx - T1 - T2;  src = Wc; dst = g_Wct; N = NHX; }
        int perA = N * 64;
        int a = t / perA, r = t % perA;
        int n = r / 64,   j = r % 64;          // j = k-pair index, k = 2j
        float f0 = src[((size_t)a * 128 + 2 * j)     * N + n];
        float f1 = src[((size_t)a * 128 + 2 * j + 1) * N + n];
        uint32_t hi, lo;
        split_pair(f0, f1, hi, lo);
        size_t half = (size_t)N * ROWB;
        unsigned char* base = dst + (size_t)a * 2 * half;
        *(uint32_t*)(base + (size_t)n * ROWB + j * 4)        = hi;
        *(uint32_t*)(base + half + (size_t)n * ROWB + j * 4) = lo;
    }
}

// ---------------------------------------------------------------------------
// k_encode: h = relu(relu(obs@W1+b1)@W2+b2) via bf16x3 mma.sync
// Block: 256 threads (8 warps), M=128 batch rows, one agent.
// smem: Ah|Al (obs, then x) 2x34816 | W1h|W1l 2x34816 | W2h|W2l 2x17408 | b1,b2
// ---------------------------------------------------------------------------
#define E_AH   0
#define E_AL   34816
#define E_W1H  69632
#define E_W1L  104448
#define E_W2H  139264
#define E_W2L  156672
#define E_B1   174080
#define E_B2   174592
#define E_SMEM 174848

__global__ __launch_bounds__(256) void k_encode(
    const float* __restrict__ obs,
    const float* __restrict__ b1, const float* __restrict__ b2)
{
    extern __shared__ unsigned char smraw[];
    const uint32_t sb = smem_u32(smraw);
    const int tid  = threadIdx.x;
    const int w    = tid >> 5;
    const int lane = tid & 31;
    const int a    = blockIdx.y;
    const int b0   = blockIdx.x * 128;

    // Stage weights (linear copies of prepped images)
    {
        const float4* s1 = (const float4*)(g_W1t + (size_t)a * 69632);
        float4* d1 = (float4*)(smraw + E_W1H);
        for (int i = tid; i < 4352; i += 256) d1[i] = s1[i];
        const float4* s2 = (const float4*)(g_W2t + (size_t)a * 34816);
        float4* d2 = (float4*)(smraw + E_W2H);
        for (int i = tid; i < 2176; i += 256) d2[i] = s2[i];
    }
    // Stage obs split hi/lo into A region
    for (int i = tid; i < 128 * 32; i += 256) {
        int m = i >> 5, kq = i & 31;                 // kq = 4-float chunk
        float4 v = *(const float4*)(obs + ((size_t)(b0 + m) * NA + a) * NOBS + kq * 4);
        uint32_t h0, l0, h1, l1;
        split_pair(v.x, v.y, h0, l0);
        split_pair(v.z, v.w, h1, l1);
        uint32_t off = (uint32_t)m * ROWB + (uint32_t)kq * 8;
        sts_v2(sb + E_AH + off, h0, h1);
        sts_v2(sb + E_AL + off, l0, l1);
    }
    if (tid < NH1) ((float*)(smraw + E_B1))[tid] = b1[a * NH1 + tid];
    if (tid < NHX) ((float*)(smraw + E_B2))[tid] = b2[a * NHX + tid];
    __syncthreads();

    // GEMM1: x[128,128] = obs @ W1 ; warp tile 64m x 32n
    {
        const int m0 = (w & 1) * 64;
        const int n0 = (w >> 1) * 32;
        float acc[4][4][4];
#pragma unroll
        for (int mi = 0; mi < 4; mi++)
#pragma unroll
            for (int ni = 0; ni < 4; ni++)
#pragma unroll
                for (int e = 0; e < 4; e++) acc[mi][ni][e] = 0.0f;

        warp_mma_bf16x3<4, 4, 8>(acc, sb + E_AH, sb + E_AL, sb + E_W1H, sb + E_W1L,
                                 m0, n0, lane);
        __syncthreads();   // everyone done reading obs tiles

        // Epilogue1: x = relu(acc + b1) -> split back into A region
        const float* b1s = (const float*)(smraw + E_B1);
#pragma unroll
        for (int mi = 0; mi < 4; mi++)
#pragma unroll
            for (int ni = 0; ni < 4; ni++) {
                int r = m0 + mi * 16 + (lane >> 2);
                int c = n0 + ni * 8 + 2 * (lane & 3);
                float bb0 = b1s[c], bb1 = b1s[c + 1];
                uint32_t hi, lo;
                float v0 = fmaxf(acc[mi][ni][0] + bb0, 0.0f);
                float v1 = fmaxf(acc[mi][ni][1] + bb1, 0.0f);
                split_pair(v0, v1, hi, lo);
                uint32_t off = (uint32_t)r * ROWB + (uint32_t)c * 2;
                sts_u32(sb + E_AH + off, hi);
                sts_u32(sb + E_AL + off, lo);
                float v2 = fmaxf(acc[mi][ni][2] + bb0, 0.0f);
                float v3 = fmaxf(acc[mi][ni][3] + bb1, 0.0f);
                split_pair(v2, v3, hi, lo);
                off += 8 * ROWB;
                sts_u32(sb + E_AH + off, hi);
                sts_u32(sb + E_AL + off, lo);
            }
    }
    __syncthreads();

    // GEMM2: h[128,64] = x @ W2 ; warp tile 32m x 32n
    {
        const int m0 = (w & 3) * 32;
        const int n0 = (w >> 2) * 32;
        float acc[2][4][4];
#pragma unroll
        for (int mi = 0; mi < 2; mi++)
#pragma unroll
            for (int ni = 0; ni < 4; ni++)
#pragma unroll
                for (int e = 0; e < 4; e++) acc[mi][ni][e] = 0.0f;

        warp_mma_bf16x3<2, 4, 8>(acc, sb + E_AH, sb + E_AL, sb + E_W2H, sb + E_W2L,
                                 m0, n0, lane);

        // Epilogue2: h = relu(acc + b2) -> g_h (float2 stores)
        const float* b2s = (const float*)(smraw + E_B2);
#pragma unroll
        for (int mi = 0; mi < 2; mi++)
#pragma unroll
            for (int ni = 0; ni < 4; ni++) {
                int r = m0 + mi * 16 + (lane >> 2);
                int c = n0 + ni * 8 + 2 * (lane & 3);
                float bb0 = b2s[c], bb1 = b2s[c + 1];
                float2 v01 = make_float2(fmaxf(acc[mi][ni][0] + bb0, 0.0f),
                                         fmaxf(acc[mi][ni][1] + bb1, 0.0f));
                float2 v23 = make_float2(fmaxf(acc[mi][ni][2] + bb0, 0.0f),
                                         fmaxf(acc[mi][ni][3] + bb1, 0.0f));
                *(float2*)(g_h + ((size_t)(b0 + r) * NA + a) * NHX + c)       = v01;
                *(float2*)(g_h + ((size_t)(b0 + r + 8) * NA + a) * NHX + c)   = v23;
            }
    }
}

// ---------------------------------------------------------------------------
// k_comm: comm[b,i,:] = sum_j M[i,j] * h[b,j,:]
// ---------------------------------------------------------------------------
__global__ __launch_bounds__(256) void k_comm() {
    __shared__ float hs[NA * NHX];
    const int tid = threadIdx.x;
    const int b = blockIdx.x;
    {
        const float4* src = (const float4*)(g_h + (size_t)b * NA * NHX);
        float4* dst = (float4*)hs;
#pragma unroll
        for (int i = tid; i < NA * NHX / 4; i += 256) dst[i] = src[i];
    }
    __syncthreads();

    const int lane = tid & 31;
    const int i0   = (tid >> 5) * 4;

    float mreg[4];
#pragma unroll
    for (int ii = 0; ii < 4; ii++) mreg[ii] = g_maskn[(i0 + ii) * NA + lane];

    float acc[4][2];
#pragma unroll
    for (int ii = 0; ii < 4; ii++) { acc[ii][0] = 0.0f; acc[ii][1] = 0.0f; }

#pragma unroll
    for (int j = 0; j < NA; j++) {
        float h0 = hs[j * NHX + lane * 2];
        float h1 = hs[j * NHX + lane * 2 + 1];
#pragma unroll
        for (int ii = 0; ii < 4; ii++) {
            float mj = __shfl_sync(0xffffffffu, mreg[ii], j);
            acc[ii][0] += mj * h0;
            acc[ii][1] += mj * h1;
        }
    }
#pragma unroll
    for (int ii = 0; ii < 4; ii++)
        *(float2*)(g_comm + ((size_t)b * NA + i0 + ii) * NHX + lane * 2) =
            make_float2(acc[ii][0], acc[ii][1]);
}

// ---------------------------------------------------------------------------
// k_final: h2 = tanh([h,comm]@Wc + bc);  q = h2@Wd + bd
// smem: Ah|Al 2x34816 (h2s overlays Ah) | Wch|Wcl 2x17408 | Wd 4096 | bc,bd
// ---------------------------------------------------------------------------
#define F_AH   0
#define F_AL   34816
#define F_WCH  69632
#define F_WCL  87040
#define F_WD   104448
#define F_BC   108544
#define F_BD   108800
#define F_SMEM 108864
#define H2S    66      // h2s fp32 row stride

__global__ __launch_bounds__(256, 2) void k_final(
    const float* __restrict__ bc, const float* __restrict__ Wd,
    const float* __restrict__ bd, float* __restrict__ q)
{
    extern __shared__ unsigned char smraw[];
    const uint32_t sbm = smem_u32(smraw);
    const int tid  = threadIdx.x;
    const int w    = tid >> 5;
    const int lane = tid & 31;
    const int a    = blockIdx.y;
    const int b0   = blockIdx.x * 128;

    // Stage Wc image, Wd, biases
    {
        const float4* s3 = (const float4*)(g_Wct + (size_t)a * 34816);
        float4* d3 = (float4*)(smraw + F_WCH);
        for (int i = tid; i < 2176; i += 256) d3[i] = s3[i];
        const float4* sw = (const float4*)(Wd + (size_t)a * NHX * NACT);
        float4* dw = (float4*)(smraw + F_WD);
        for (int i = tid; i < 256; i += 256) dw[i] = sw[i];
    }
    // Stage concat [h | comm] split hi/lo: k 0..63 = h, 64..127 = comm
    for (int i = tid; i < 128 * 32; i += 256) {
        int m = i >> 5, cchunk = i & 31;
        const float* src; int k0;
        if (cchunk < 16) { src = g_h;    k0 = cchunk * 4; }
        else             { src = g_comm; k0 = 64 + (cchunk - 16) * 4; }
        float4 v = *(const float4*)(src + ((size_t)(b0 + m) * NA + a) * NHX + (k0 & 63));
        uint32_t h0, l0, h1, l1;
        split_pair(v.x, v.y, h0, l0);
        split_pair(v.z, v.w, h1, l1);
        uint32_t off = (uint32_t)m * ROWB + (uint32_t)k0 * 2;
        sts_v2(sbm + F_AH + off, h0, h1);
        sts_v2(sbm + F_AL + off, l0, l1);
    }
    if (tid < NHX)  ((float*)(smraw + F_BC))[tid] = bc[a * NHX + tid];
    if (tid < NACT) ((float*)(smraw + F_BD))[tid] = bd[a * NACT + tid];
    __syncthreads();

    // GEMM3: pre[128,64] = concat @ Wc ; warp tile 32m x 32n
    float acc[2][4][4];
#pragma unroll
    for (int mi = 0; mi < 2; mi++)
#pragma unroll
        for (int ni = 0; ni < 4; ni++)
#pragma unroll
            for (int e = 0; e < 4; e++) acc[mi][ni][e] = 0.0f;

    const int m0 = (w & 3) * 32;
    const int n0 = (w >> 2) * 32;
    warp_mma_bf16x3<2, 4, 8>(acc, sbm + F_AH, sbm + F_AL, sbm + F_WCH, sbm + F_WCL,
                             m0, n0, lane);
    __syncthreads();   // all warps done reading A tiles before h2s overlay

    // Epilogue3: h2 = tanh(acc + bc) -> h2s fp32 [128][66] (overlays A region)
    {
        const float* bcs = (const float*)(smraw + F_BC);
        float* h2s = (float*)(smraw + F_AH);
#pragma unroll
        for (int mi = 0; mi < 2; mi++)
#pragma unroll
            for (int ni = 0; ni < 4; ni++) {
                int r = m0 + mi * 16 + (lane >> 2);
                int c = n0 + ni * 8 + 2 * (lane & 3);
                float bb0 = bcs[c], bb1 = bcs[c + 1];
                *(float2*)(h2s + r * H2S + c) =
                    make_float2(tanhf(acc[mi][ni][0] + bb0), tanhf(acc[mi][ni][1] + bb1));
                *(float2*)(h2s + (r + 8) * H2S + c) =
                    make_float2(tanhf(acc[mi][ni][2] + bb0), tanhf(acc[mi][ni][3] + bb1));
            }
    }
    __syncthreads();

    // GEMM4 (scalar): q[m, g*8..g*8+7] = h2[m,:] @ Wd + bd
    {
        const float* h2s = (const float*)(smraw + F_AH);
        const float* wds = (const float*)(smraw + F_WD);
        const float* bds = (const float*)(smraw + F_BD);
        const int m = tid & 127;
        const int g = tid >> 7;
        float accq[8];
#pragma unroll
        for (int j = 0; j < 8; j++) accq[j] = bds[g * 8 + j];
        const float* h2r = h2s + m * H2S;
#pragma unroll 4
        for (int k = 0; k < NHX; k++) {
            float av = h2r[k];
            float4 w0 = *(const float4*)(wds + k * NACT + g * 8);
            float4 w1 = *(const float4*)(wds + k * NACT + g * 8 + 4);
            accq[0] += av * w0.x; accq[1] += av * w0.y;
            accq[2] += av * w0.z; accq[3] += av * w0.w;
            accq[4] += av * w1.x; accq[5] += av * w1.y;
            accq[6] += av * w1.z; accq[7] += av * w1.w;
        }
        float* qrow = q + ((size_t)(b0 + m) * NA + a) * NACT + g * 8;
        *(float4*)qrow       = make_float4(accq[0], accq[1], accq[2], accq[3]);
        *(float4*)(qrow + 4) = make_float4(accq[4], accq[5], accq[6], accq[7]);
    }
}

// ---------------------------------------------------------------------------
extern "C" void kernel_launch(void* const* d_in, const int* in_sizes, int n_in,
                              void* d_out, int out_size) {
    const float* obs = (const float*)d_in[0];
    const float* W1  = (const float*)d_in[1];
    const float* b1  = (const float*)d_in[2];
    const float* W2  = (const float*)d_in[3];
    const float* b2  = (const float*)d_in[4];
    // d_in[5], d_in[6]: Wg, bg — dead code (gates never reach the output)
    const float* Wc  = (const float*)d_in[7];
    const float* bc  = (const float*)d_in[8];
    const float* Wd  = (const float*)d_in[9];
    const float* bd  = (const float*)d_in[10];
    const int*   cm  = (const int*)d_in[11];
    float* q = (float*)d_out;

    cudaFuncSetAttribute(k_encode, cudaFuncAttributeMaxDynamicSharedMemorySize, E_SMEM);
    cudaFuncSetAttribute(k_final,  cudaFuncAttributeMaxDynamicSharedMemorySize, F_SMEM);

    k_mask<<<1, 32>>>(cm);
    k_prep<<<256, 256>>>(W1, W2, Wc);
    k_encode<<<dim3(NB / 128, NA), 256, E_SMEM>>>(obs, b1, b2);
    k_comm<<<NB, 256>>>();
    k_final<<<dim3(NB / 128, NA), 256, F_SMEM>>>(bc, Wd, bd, q);
}

// round 13
// speedup vs baseline: 3.2384x; 2.3369x over previous
#include <cuda_runtime.h>
#include <cuda_fp16.h>
#include <math.h>
#include <stdint.h>

#define NB   8192
#define NA   32
#define NOBS 128
#define NH1  128
#define NHX  64
#define NACT 16

#define ROWB   272          // bytes per padded row (136 halfs)
#define ROW8B  2176         // 8 rows

// ---------------------------------------------------------------------------
// Scratch + prepped weight images (allocation-free rule: __device__ globals)
// g_h2/g_c2: half2-packed activations [b][a][32 u32]
// ---------------------------------------------------------------------------
__device__ unsigned int g_h2[NB * NA * 32];      // 32 MB
__device__ unsigned int g_c2[NB * NA * 32];      // 32 MB
__device__ float g_maskn[NA * NA];
// Transposed fp16 weight images, pad-136 rows: image[n][k] = W[k][n]
__device__ unsigned char g_W1t[NA * NH1 * ROWB];   // 34816 B / agent
__device__ unsigned char g_W2t[NA * NHX * ROWB];   // 17408 B / agent
__device__ unsigned char g_Wct[NA * NHX * ROWB];   // 17408 B / agent
__device__ unsigned char g_Wdt[NA * NACT * ROWB];  //  4352 B / agent

// ---------------------------------------------------------------------------
// Helpers
// ---------------------------------------------------------------------------
__device__ __forceinline__ uint32_t smem_u32(const void* p) {
    uint32_t a;
    asm("{ .reg .u64 t; cvta.to.shared.u64 t, %1; cvt.u32.u64 %0, t; }"
        : "=r"(a) : "l"(p));
    return a;
}
__device__ __forceinline__ uint32_t lds_u32(uint32_t addr) {
    uint32_t v; asm volatile("ld.shared.b32 %0, [%1];" : "=r"(v) : "r"(addr)); return v;
}
__device__ __forceinline__ void sts_u32(uint32_t addr, uint32_t v) {
    asm volatile("st.shared.b32 [%0], %1;" :: "r"(addr), "r"(v));
}
__device__ __forceinline__ void sts_v2(uint32_t addr, uint32_t a, uint32_t b) {
    asm volatile("st.shared.v2.b32 [%0], {%1,%2};" :: "r"(addr), "r"(a), "r"(b));
}
// d += a * b  (fp16 MMA, fp32 accumulate)
__device__ __forceinline__ void mma16816(float d[4], const uint32_t a[4], const uint32_t b[2]) {
    asm volatile(
        "mma.sync.aligned.m16n8k16.row.col.f32.f16.f16.f32 "
        "{%0,%1,%2,%3}, {%4,%5,%6,%7}, {%8,%9}, {%0,%1,%2,%3};"
        : "+f"(d[0]), "+f"(d[1]), "+f"(d[2]), "+f"(d[3])
        : "r"(a[0]), "r"(a[1]), "r"(a[2]), "r"(a[3]), "r"(b[0]), "r"(b[1]));
}
__device__ __forceinline__ uint32_t pack_h2(float f0, float f1) {
    __half2 h = __floats2half2_rn(f0, f1);
    return *(const uint32_t*)&h;
}
__device__ __forceinline__ float2 unpack_h2(uint32_t u) {
    return __half22float2(*(const __half2*)&u);
}

// Warp-level fp16 GEMM: acc[MT][NT][4] += A(m0..)@B(n0..)^T, K = K16*16.
// Pad-136 layout for A and B; fragment addressing verified in R11/R12.
template<int MT, int NT, int K16>
__device__ __forceinline__ void warp_mma_f16(
    float (&acc)[MT][NT][4],
    uint32_t sA, uint32_t sB, int m0, int n0, int lane)
{
    const uint32_t laneOff = (uint32_t)((lane >> 2) * ROWB + (lane & 3) * 4);
#pragma unroll
    for (int ks = 0; ks < K16; ks++) {
        uint32_t af[MT][4];
#pragma unroll
        for (int mi = 0; mi < MT; mi++) {
            uint32_t ab = sA + (uint32_t)(m0 + mi * 16) * ROWB + (uint32_t)ks * 32 + laneOff;
            af[mi][0] = lds_u32(ab);
            af[mi][1] = lds_u32(ab + ROW8B);
            af[mi][2] = lds_u32(ab + 16);
            af[mi][3] = lds_u32(ab + ROW8B + 16);
        }
#pragma unroll
        for (int ni = 0; ni < NT; ni++) {
            uint32_t bb = sB + (uint32_t)(n0 + ni * 8) * ROWB + (uint32_t)ks * 32 + laneOff;
            uint32_t bf[2];
            bf[0] = lds_u32(bb);
            bf[1] = lds_u32(bb + 16);
#pragma unroll
            for (int mi = 0; mi < MT; mi++)
                mma16816(acc[mi][ni], af[mi], bf);
        }
    }
}

// ---------------------------------------------------------------------------
// k_mask
// ---------------------------------------------------------------------------
__global__ void k_mask(const int* __restrict__ cm) {
    int i = threadIdx.x;
    if (i >= NA) return;
    int cnt = 0;
#pragma unroll
    for (int j = 0; j < NA; j++)
        cnt += (j != i && cm[i * NA + j] != 0) ? 1 : 0;
    float inv = 1.0f / (float)(cnt > 0 ? cnt : 1);
#pragma unroll
    for (int j = 0; j < NA; j++)
        g_maskn[i * NA + j] = (j != i && cm[i * NA + j] != 0) ? inv : 0.0f;
}

// ---------------------------------------------------------------------------
// k_prep: W -> transposed fp16 images (image[n][2j..2j+1] = W[2j..2j+1][n])
// ---------------------------------------------------------------------------
__global__ void k_prep(const float* __restrict__ W1,
                       const float* __restrict__ W2,
                       const float* __restrict__ Wc,
                       const float* __restrict__ Wd) {
    const int T1 = NA * NH1 * 64;    // W1: n=128, 64 k-pairs
    const int T2 = NA * NHX * 64;    // W2 / Wc: n=64, 64 k-pairs
    const int T4 = NA * NACT * 32;   // Wd: n=16, 32 k-pairs (K=64)
    const int total = T1 + 2 * T2 + T4;
    for (int idx = blockIdx.x * blockDim.x + threadIdx.x; idx < total;
         idx += gridDim.x * blockDim.x) {
        const float* src; unsigned char* dst; int N, JP, K; int t;
        if (idx < T1)                { t = idx;                src = W1; dst = g_W1t; N = NH1;  JP = 64; K = 128; }
        else if (idx < T1 + T2)      { t = idx - T1;           src = W2; dst = g_W2t; N = NHX;  JP = 64; K = 128; }
        else if (idx < T1 + 2 * T2)  { t = idx - T1 - T2;      src = Wc; dst = g_Wct; N = NHX;  JP = 64; K = 128; }
        else                         { t = idx - T1 - 2 * T2;  src = Wd; dst = g_Wdt; N = NACT; JP = 32; K = 64;  }
        int perA = N * JP;
        int a = t / perA, r = t % perA;
        int n = r / JP,   j = r % JP;
        float f0 = src[((size_t)a * K + 2 * j)     * N + n];
        float f1 = src[((size_t)a * K + 2 * j + 1) * N + n];
        unsigned char* base = dst + (size_t)a * N * ROWB;
        *(uint32_t*)(base + (size_t)n * ROWB + j * 4) = pack_h2(f0, f1);
    }
}

// ---------------------------------------------------------------------------
// k_encode: h = relu(relu(obs@W1+b1)@W2+b2), fp16 mma.sync, M=128/block
// smem: A 34816 | W1 34816 | W2 17408 | b1 512 | b2 256
// ---------------------------------------------------------------------------
#define E_A    0
#define E_W1   34816
#define E_W2   69632
#define E_B1   87040
#define E_B2   87552
#define E_SMEM 87808

__global__ __launch_bounds__(256) void k_encode(
    const float* __restrict__ obs,
    const float* __restrict__ b1, const float* __restrict__ b2)
{
    extern __shared__ unsigned char smraw[];
    const uint32_t sb = smem_u32(smraw);
    const int tid  = threadIdx.x;
    const int w    = tid >> 5;
    const int lane = tid & 31;
    const int a    = blockIdx.y;
    const int b0   = blockIdx.x * 128;

    // Stage weight images (linear float4 copies)
    {
        const float4* s1 = (const float4*)(g_W1t + (size_t)a * 34816);
        float4* d1 = (float4*)(smraw + E_W1);
        for (int i = tid; i < 2176; i += 256) d1[i] = s1[i];
        const float4* s2 = (const float4*)(g_W2t + (size_t)a * 17408);
        float4* d2 = (float4*)(smraw + E_W2);
        for (int i = tid; i < 1088; i += 256) d2[i] = s2[i];
    }
    // Stage obs as fp16 rows (128 halfs)
    for (int i = tid; i < 128 * 32; i += 256) {
        int m = i >> 5, kq = i & 31;             // kq = 4-float chunk
        float4 v = *(const float4*)(obs + ((size_t)(b0 + m) * NA + a) * NOBS + kq * 4);
        sts_v2(sb + E_A + (uint32_t)m * ROWB + (uint32_t)kq * 8,
               pack_h2(v.x, v.y), pack_h2(v.z, v.w));
    }
    if (tid < NH1) ((float*)(smraw + E_B1))[tid] = b1[a * NH1 + tid];
    if (tid < NHX) ((float*)(smraw + E_B2))[tid] = b2[a * NHX + tid];
    __syncthreads();

    // GEMM1: x[128,128] = obs @ W1^T-image ; warp tile 64m x 32n
    {
        const int m0 = (w & 1) * 64;
        const int n0 = (w >> 1) * 32;
        float acc[4][4][4];
#pragma unroll
        for (int mi = 0; mi < 4; mi++)
#pragma unroll
            for (int ni = 0; ni < 4; ni++)
#pragma unroll
                for (int e = 0; e < 4; e++) acc[mi][ni][e] = 0.0f;

        warp_mma_f16<4, 4, 8>(acc, sb + E_A, sb + E_W1, m0, n0, lane);
        __syncthreads();   // all warps done reading obs tiles

        // Epilogue1: x = relu(acc + b1) -> fp16 back into A region
        const float* b1s = (const float*)(smraw + E_B1);
#pragma unroll
        for (int mi = 0; mi < 4; mi++)
#pragma unroll
            for (int ni = 0; ni < 4; ni++) {
                int r = m0 + mi * 16 + (lane >> 2);
                int c = n0 + ni * 8 + 2 * (lane & 3);
                float bb0 = b1s[c], bb1 = b1s[c + 1];
                uint32_t off = (uint32_t)r * ROWB + (uint32_t)c * 2;
                sts_u32(sb + E_A + off,
                        pack_h2(fmaxf(acc[mi][ni][0] + bb0, 0.0f),
                                fmaxf(acc[mi][ni][1] + bb1, 0.0f)));
                sts_u32(sb + E_A + off + 8 * ROWB,
                        pack_h2(fmaxf(acc[mi][ni][2] + bb0, 0.0f),
                                fmaxf(acc[mi][ni][3] + bb1, 0.0f)));
            }
    }
    __syncthreads();

    // GEMM2: h[128,64] = x @ W2^T-image ; warp tile 32m x 32n
    {
        const int m0 = (w & 3) * 32;
        const int n0 = (w >> 2) * 32;
        float acc[2][4][4];
#pragma unroll
        for (int mi = 0; mi < 2; mi++)
#pragma unroll
            for (int ni = 0; ni < 4; ni++)
#pragma unroll
                for (int e = 0; e < 4; e++) acc[mi][ni][e] = 0.0f;

        warp_mma_f16<2, 4, 8>(acc, sb + E_A, sb + E_W2, m0, n0, lane);

        // Epilogue2: h = relu(acc + b2) -> g_h2 (half2 u32)
        const float* b2s = (const float*)(smraw + E_B2);
#pragma unroll
        for (int mi = 0; mi < 2; mi++)
#pragma unroll
            for (int ni = 0; ni < 4; ni++) {
                int r = m0 + mi * 16 + (lane >> 2);
                int c = n0 + ni * 8 + 2 * (lane & 3);   // even
                float bb0 = b2s[c], bb1 = b2s[c + 1];
                g_h2[((size_t)(b0 + r) * NA + a) * 32 + (c >> 1)] =
                    pack_h2(fmaxf(acc[mi][ni][0] + bb0, 0.0f),
                            fmaxf(acc[mi][ni][1] + bb1, 0.0f));
                g_h2[((size_t)(b0 + r + 8) * NA + a) * 32 + (c >> 1)] =
                    pack_h2(fmaxf(acc[mi][ni][2] + bb0, 0.0f),
                            fmaxf(acc[mi][ni][3] + bb1, 0.0f));
            }
    }
}

// ---------------------------------------------------------------------------
// k_comm: comm[b,i,:] = sum_j M[i,j]*h[b,j,:]  (half2 in/out, fp32 math)
// ---------------------------------------------------------------------------
__global__ __launch_bounds__(256) void k_comm() {
    __shared__ uint32_t hs[NA * 32];
    const int tid = threadIdx.x;
    const int b = blockIdx.x;
    {
        const uint4* src = (const uint4*)(g_h2 + (size_t)b * NA * 32);
        uint4* dst = (uint4*)hs;
#pragma unroll
        for (int i = tid; i < NA * 8; i += 256) dst[i] = src[i];
    }
    __syncthreads();

    const int lane = tid & 31;
    const int i0   = (tid >> 5) * 4;

    float mreg[4];
#pragma unroll
    for (int ii = 0; ii < 4; ii++) mreg[ii] = g_maskn[(i0 + ii) * NA + lane];

    float acc[4][2];
#pragma unroll
    for (int ii = 0; ii < 4; ii++) { acc[ii][0] = 0.0f; acc[ii][1] = 0.0f; }

#pragma unroll
    for (int j = 0; j < NA; j++) {
        float2 h = unpack_h2(hs[j * 32 + lane]);
#pragma unroll
        for (int ii = 0; ii < 4; ii++) {
            float mj = __shfl_sync(0xffffffffu, mreg[ii], j);
            acc[ii][0] += mj * h.x;
            acc[ii][1] += mj * h.y;
        }
    }
#pragma unroll
    for (int ii = 0; ii < 4; ii++)
        g_c2[((size_t)b * NA + i0 + ii) * 32 + lane] = pack_h2(acc[ii][0], acc[ii][1]);
}

// ---------------------------------------------------------------------------
// k_final: h2 = tanh([h,comm]@Wc + bc); q = h2@Wd + bd (both via mma)
// smem: A 34816 | Wc 17408 | Wd 4352 | bc 256 | bd 64
// ---------------------------------------------------------------------------
#define F_A    0
#define F_WC   34816
#define F_WDT  52224
#define F_BC   56576
#define F_BD   56832
#define F_SMEM 56896

__global__ __launch_bounds__(256) void k_final(
    const float* __restrict__ bc, const float* __restrict__ bd,
    float* __restrict__ q)
{
    extern __shared__ unsigned char smraw[];
    const uint32_t sbm = smem_u32(smraw);
    const int tid  = threadIdx.x;
    const int w    = tid >> 5;
    const int lane = tid & 31;
    const int a    = blockIdx.y;
    const int b0   = blockIdx.x * 128;

    // Stage weight images
    {
        const float4* s3 = (const float4*)(g_Wct + (size_t)a * 17408);
        float4* d3 = (float4*)(smraw + F_WC);
        for (int i = tid; i < 1088; i += 256) d3[i] = s3[i];
        const float4* s4 = (const float4*)(g_Wdt + (size_t)a * 4352);
        float4* d4 = (float4*)(smraw + F_WDT);
        for (int i = tid; i < 272; i += 256) d4[i] = s4[i];
    }
    // Stage concat [h | comm] rows: raw u32 copies (already fp16)
    for (int i = tid; i < 128 * 64; i += 256) {
        int m = i >> 6, j = i & 63;
        uint32_t v = (j < 32)
            ? g_h2[((size_t)(b0 + m) * NA + a) * 32 + j]
            : g_c2[((size_t)(b0 + m) * NA + a) * 32 + (j - 32)];
        sts_u32(sbm + F_A + (uint32_t)m * ROWB + (uint32_t)j * 4, v);
    }
    if (tid < NHX)  ((float*)(smraw + F_BC))[tid] = bc[a * NHX + tid];
    if (tid < NACT) ((float*)(smraw + F_BD))[tid] = bd[a * NACT + tid];
    __syncthreads();

    // GEMM3: pre[128,64] = concat @ Wc^T-image ; warp tile 32m x 32n
    {
        float acc[2][4][4];
#pragma unroll
        for (int mi = 0; mi < 2; mi++)
#pragma unroll
            for (int ni = 0; ni < 4; ni++)
#pragma unroll
                for (int e = 0; e < 4; e++) acc[mi][ni][e] = 0.0f;

        const int m0 = (w & 3) * 32;
        const int n0 = (w >> 2) * 32;
        warp_mma_f16<2, 4, 8>(acc, sbm + F_A, sbm + F_WC, m0, n0, lane);
        __syncthreads();   // done reading concat tiles

        // Epilogue3: h2 = tanh(acc + bc) -> fp16 into A region (k 0..63)
        const float* bcs = (const float*)(smraw + F_BC);
#pragma unroll
        for (int mi = 0; mi < 2; mi++)
#pragma unroll
            for (int ni = 0; ni < 4; ni++) {
                int r = m0 + mi * 16 + (lane >> 2);
                int c = n0 + ni * 8 + 2 * (lane & 3);
                float bb0 = bcs[c], bb1 = bcs[c + 1];
                uint32_t off = (uint32_t)r * ROWB + (uint32_t)c * 2;
                sts_u32(sbm + F_A + off,
                        pack_h2(tanhf(acc[mi][ni][0] + bb0), tanhf(acc[mi][ni][1] + bb1)));
                sts_u32(sbm + F_A + off + 8 * ROWB,
                        pack_h2(tanhf(acc[mi][ni][2] + bb0), tanhf(acc[mi][ni][3] + bb1)));
            }
    }
    __syncthreads();

    // GEMM4: q[128,16] = h2 @ Wd^T-image ; warp w -> rows w*16..w*16+15, K=64
    {
        float acc[1][2][4];
#pragma unroll
        for (int ni = 0; ni < 2; ni++)
#pragma unroll
            for (int e = 0; e < 4; e++) acc[0][ni][e] = 0.0f;

        warp_mma_f16<1, 2, 4>(acc, sbm + F_A, sbm + F_WDT, w * 16, 0, lane);

        const float* bds = (const float*)(smraw + F_BD);
#pragma unroll
        for (int ni = 0; ni < 2; ni++) {
            int r = w * 16 + (lane >> 2);
            int c = ni * 8 + 2 * (lane & 3);
            float bb0 = bds[c], bb1 = bds[c + 1];
            *(float2*)(q + ((size_t)(b0 + r) * NA + a) * NACT + c) =
                make_float2(acc[0][ni][0] + bb0, acc[0][ni][1] + bb1);
            *(float2*)(q + ((size_t)(b0 + r + 8) * NA + a) * NACT + c) =
                make_float2(acc[0][ni][2] + bb0, acc[0][ni][3] + bb1);
        }
    }
}

// ---------------------------------------------------------------------------
extern "C" void kernel_launch(void* const* d_in, const int* in_sizes, int n_in,
                              void* d_out, int out_size) {
    const float* obs = (const float*)d_in[0];
    const float* W1  = (const float*)d_in[1];
    const float* b1  = (const float*)d_in[2];
    const float* W2  = (const float*)d_in[3];
    const float* b2  = (const float*)d_in[4];
    // d_in[5], d_in[6]: Wg, bg — dead code (gates never reach the output)
    const float* Wc  = (const float*)d_in[7];
    const float* bc  = (const float*)d_in[8];
    const float* Wd  = (const float*)d_in[9];
    const float* bd  = (const float*)d_in[10];
    const int*   cm  = (const int*)d_in[11];
    float* q = (float*)d_out;

    cudaFuncSetAttribute(k_encode, cudaFuncAttributeMaxDynamicSharedMemorySize, E_SMEM);
    cudaFuncSetAttribute(k_final,  cudaFuncAttributeMaxDynamicSharedMemorySize, F_SMEM);

    k_mask<<<1, 32>>>(cm);
    k_prep<<<256, 256>>>(W1, W2, Wc, Wd);
    k_encode<<<dim3(NB / 128, NA), 256, E_SMEM>>>(obs, b1, b2);
    k_comm<<<NB, 256>>>();
    k_final<<<dim3(NB / 128, NA), 256, F_SMEM>>>(bc, bd, q);
}

// round 14
// speedup vs baseline: 3.4952x; 1.0793x over previous
#include <cuda_runtime.h>
#include <cuda_fp16.h>
#include <math.h>
#include <stdint.h>

#define NB   8192
#define NA   32
#define NOBS 128
#define NH1  128
#define NHX  64
#define NACT 16

#define ROWB   272          // bytes per padded row (136 halfs); 16B-aligned, ldsm conflict-free

// ---------------------------------------------------------------------------
// Scratch + prepped weight images (allocation-free rule: __device__ globals)
// ---------------------------------------------------------------------------
__device__ unsigned int g_h2[NB * NA * 32];      // h  activations, half2-packed
__device__ unsigned int g_c2[NB * NA * 32];      // comm, half2-packed
__device__ unsigned int g_m16[2 * 32 * 16];      // M hi|lo fp16 images [t][i][jpair]
// Transposed fp16 weight images, pad-136 rows: image[n][k] = W[k][n]
__device__ unsigned char g_W1t[NA * NH1 * ROWB];
__device__ unsigned char g_W2t[NA * NHX * ROWB];
__device__ unsigned char g_Wct[NA * NHX * ROWB];
__device__ unsigned char g_Wdt[NA * NACT * ROWB];

// ---------------------------------------------------------------------------
// Helpers
// ---------------------------------------------------------------------------
__device__ __forceinline__ uint32_t smem_u32(const void* p) {
    uint32_t a;
    asm("{ .reg .u64 t; cvta.to.shared.u64 t, %1; cvt.u32.u64 %0, t; }"
        : "=r"(a) : "l"(p));
    return a;
}
__device__ __forceinline__ void sts_u32(uint32_t addr, uint32_t v) {
    asm volatile("st.shared.b32 [%0], %1;" :: "r"(addr), "r"(v));
}
__device__ __forceinline__ void sts_v2(uint32_t addr, uint32_t a, uint32_t b) {
    asm volatile("st.shared.v2.b32 [%0], {%1,%2};" :: "r"(addr), "r"(a), "r"(b));
}
__device__ __forceinline__ void ldsm_x4(uint32_t &r0, uint32_t &r1, uint32_t &r2,
                                        uint32_t &r3, uint32_t addr) {
    asm volatile("ldmatrix.sync.aligned.m8n8.x4.shared.b16 {%0,%1,%2,%3}, [%4];"
                 : "=r"(r0), "=r"(r1), "=r"(r2), "=r"(r3) : "r"(addr));
}
__device__ __forceinline__ void ldsm_x4_t(uint32_t &r0, uint32_t &r1, uint32_t &r2,
                                          uint32_t &r3, uint32_t addr) {
    asm volatile("ldmatrix.sync.aligned.m8n8.x4.trans.shared.b16 {%0,%1,%2,%3}, [%4];"
                 : "=r"(r0), "=r"(r1), "=r"(r2), "=r"(r3) : "r"(addr));
}
// d += a * b  (fp16 MMA, fp32 accumulate)
__device__ __forceinline__ void mma16816(float d[4], const uint32_t a[4], const uint32_t b[2]) {
    asm volatile(
        "mma.sync.aligned.m16n8k16.row.col.f32.f16.f16.f32 "
        "{%0,%1,%2,%3}, {%4,%5,%6,%7}, {%8,%9}, {%0,%1,%2,%3};"
        : "+f"(d[0]), "+f"(d[1]), "+f"(d[2]), "+f"(d[3])
        : "r"(a[0]), "r"(a[1]), "r"(a[2]), "r"(a[3]), "r"(b[0]), "r"(b[1]));
}
__device__ __forceinline__ uint32_t pack_h2(float f0, float f1) {
    __half2 h = __floats2half2_rn(f0, f1);
    return *(const uint32_t*)&h;
}

// Warp-level fp16 GEMM via ldmatrix: acc[MT][NT][4] += A(m0..) @ B(n0..)^T.
// NT must be even. Pad-136 layout for A and B (addressing verified R11-R13).
template<int MT, int NT, int K16>
__device__ __forceinline__ void warp_mma_f16(
    float (&acc)[MT][NT][4],
    uint32_t sA, uint32_t sB, int m0, int n0, int lane)
{
    // A lanes: bit3 -> row+8 (matrix1: m8-15), bit4 -> col+16B (matrix2/3: k8-15)
    const uint32_t aOff = (uint32_t)((lane & 7) + ((lane >> 3) & 1) * 8) * ROWB
                        + (uint32_t)((lane >> 4) & 1) * 16;
    // B lanes: bit3 -> col+16B (matrix1: k8-15), bit4 -> row+8 (matrix2/3: n8-15)
    const uint32_t bOff = (uint32_t)((lane & 7) + ((lane >> 4) & 1) * 8) * ROWB
                        + (uint32_t)((lane >> 3) & 1) * 16;
#pragma unroll
    for (int ks = 0; ks < K16; ks++) {
        uint32_t af[MT][4];
#pragma unroll
        for (int mi = 0; mi < MT; mi++)
            ldsm_x4(af[mi][0], af[mi][1], af[mi][2], af[mi][3],
                    sA + (uint32_t)(m0 + mi * 16) * ROWB + (uint32_t)ks * 32 + aOff);
        uint32_t bf[NT][2];
#pragma unroll
        for (int nj = 0; nj < NT / 2; nj++)
            ldsm_x4(bf[2 * nj][0], bf[2 * nj][1], bf[2 * nj + 1][0], bf[2 * nj + 1][1],
                    sB + (uint32_t)(n0 + nj * 16) * ROWB + (uint32_t)ks * 32 + bOff);
#pragma unroll
        for (int ni = 0; ni < NT; ni++)
#pragma unroll
            for (int mi = 0; mi < MT; mi++)
                mma16816(acc[mi][ni], af[mi], bf[ni]);
    }
}

// ---------------------------------------------------------------------------
// k_mask: M = offdiag_mask / max(cnt,1) -> fp16 hi/lo images [t][i][jpair]
// ---------------------------------------------------------------------------
__global__ void k_mask(const int* __restrict__ cm) {
    int i = threadIdx.x;
    if (i >= NA) return;
    int cnt = 0;
#pragma unroll
    for (int j = 0; j < NA; j++)
        cnt += (j != i && cm[i * NA + j] != 0) ? 1 : 0;
    float inv = 1.0f / (float)(cnt > 0 ? cnt : 1);
#pragma unroll
    for (int jp = 0; jp < 16; jp++) {
        float f0 = (2 * jp     != i && cm[i * NA + 2 * jp]     != 0) ? inv : 0.0f;
        float f1 = (2 * jp + 1 != i && cm[i * NA + 2 * jp + 1] != 0) ? inv : 0.0f;
        __half h0 = __float2half_rn(f0);
        __half h1 = __float2half_rn(f1);
        float l0 = f0 - __half2float(h0);
        float l1 = f1 - __half2float(h1);
        g_m16[i * 16 + jp] =
            ((uint32_t)__half_as_ushort(h1) << 16) | (uint32_t)__half_as_ushort(h0);
        g_m16[512 + i * 16 + jp] = pack_h2(l0, l1);
    }
}

// ---------------------------------------------------------------------------
// k_prep: W -> transposed fp16 images (image[n][2j..2j+1] = W[2j..2j+1][n])
// ---------------------------------------------------------------------------
__global__ void k_prep(const float* __restrict__ W1,
                       const float* __restrict__ W2,
                       const float* __restrict__ Wc,
                       const float* __restrict__ Wd) {
    const int T1 = NA * NH1 * 64;
    const int T2 = NA * NHX * 64;
    const int T4 = NA * NACT * 32;
    const int total = T1 + 2 * T2 + T4;
    for (int idx = blockIdx.x * blockDim.x + threadIdx.x; idx < total;
         idx += gridDim.x * blockDim.x) {
        const float* src; unsigned char* dst; int N, JP, K; int t;
        if (idx < T1)                { t = idx;                src = W1; dst = g_W1t; N = NH1;  JP = 64; K = 128; }
        else if (idx < T1 + T2)      { t = idx - T1;           src = W2; dst = g_W2t; N = NHX;  JP = 64; K = 128; }
        else if (idx < T1 + 2 * T2)  { t = idx - T1 - T2;      src = Wc; dst = g_Wct; N = NHX;  JP = 64; K = 128; }
        else                         { t = idx - T1 - 2 * T2;  src = Wd; dst = g_Wdt; N = NACT; JP = 32; K = 64;  }
        int perA = N * JP;
        int a = t / perA, r = t % perA;
        int n = r / JP,   j = r % JP;
        float f0 = src[((size_t)a * K + 2 * j)     * N + n];
        float f1 = src[((size_t)a * K + 2 * j + 1) * N + n];
        unsigned char* base = dst + (size_t)a * N * ROWB;
        *(uint32_t*)(base + (size_t)n * ROWB + j * 4) = pack_h2(f0, f1);
    }
}

// ---------------------------------------------------------------------------
// k_encode: h = relu(relu(obs@W1+b1)@W2+b2), fp16 mma, M=128/block
// ---------------------------------------------------------------------------
#define E_A    0
#define E_W1   34816
#define E_W2   69632
#define E_B1   87040
#define E_B2   87552
#define E_SMEM 87808

__global__ __launch_bounds__(256) void k_encode(
    const float* __restrict__ obs,
    const float* __restrict__ b1, const float* __restrict__ b2)
{
    extern __shared__ unsigned char smraw[];
    const uint32_t sb = smem_u32(smraw);
    const int tid  = threadIdx.x;
    const int w    = tid >> 5;
    const int lane = tid & 31;
    const int a    = blockIdx.y;
    const int b0   = blockIdx.x * 128;

    {
        const float4* s1 = (const float4*)(g_W1t + (size_t)a * 34816);
        float4* d1 = (float4*)(smraw + E_W1);
        for (int i = tid; i < 2176; i += 256) d1[i] = s1[i];
        const float4* s2 = (const float4*)(g_W2t + (size_t)a * 17408);
        float4* d2 = (float4*)(smraw + E_W2);
        for (int i = tid; i < 1088; i += 256) d2[i] = s2[i];
    }
    for (int i = tid; i < 128 * 32; i += 256) {
        int m = i >> 5, kq = i & 31;
        float4 v = *(const float4*)(obs + ((size_t)(b0 + m) * NA + a) * NOBS + kq * 4);
        sts_v2(sb + E_A + (uint32_t)m * ROWB + (uint32_t)kq * 8,
               pack_h2(v.x, v.y), pack_h2(v.z, v.w));
    }
    if (tid < NH1) ((float*)(smraw + E_B1))[tid] = b1[a * NH1 + tid];
    if (tid < NHX) ((float*)(smraw + E_B2))[tid] = b2[a * NHX + tid];
    __syncthreads();

    // GEMM1: x[128,128] ; warp tile 64m x 32n
    {
        const int m0 = (w & 1) * 64;
        const int n0 = (w >> 1) * 32;
        float acc[4][4][4];
#pragma unroll
        for (int mi = 0; mi < 4; mi++)
#pragma unroll
            for (int ni = 0; ni < 4; ni++)
#pragma unroll
                for (int e = 0; e < 4; e++) acc[mi][ni][e] = 0.0f;

        warp_mma_f16<4, 4, 8>(acc, sb + E_A, sb + E_W1, m0, n0, lane);
        __syncthreads();

        const float* b1s = (const float*)(smraw + E_B1);
#pragma unroll
        for (int mi = 0; mi < 4; mi++)
#pragma unroll
            for (int ni = 0; ni < 4; ni++) {
                int r = m0 + mi * 16 + (lane >> 2);
                int c = n0 + ni * 8 + 2 * (lane & 3);
                float bb0 = b1s[c], bb1 = b1s[c + 1];
                uint32_t off = (uint32_t)r * ROWB + (uint32_t)c * 2;
                sts_u32(sb + E_A + off,
                        pack_h2(fmaxf(acc[mi][ni][0] + bb0, 0.0f),
                                fmaxf(acc[mi][ni][1] + bb1, 0.0f)));
                sts_u32(sb + E_A + off + 8 * ROWB,
                        pack_h2(fmaxf(acc[mi][ni][2] + bb0, 0.0f),
                                fmaxf(acc[mi][ni][3] + bb1, 0.0f)));
            }
    }
    __syncthreads();

    // GEMM2: h[128,64] ; warp tile 32m x 32n
    {
        const int m0 = (w & 3) * 32;
        const int n0 = (w >> 2) * 32;
        float acc[2][4][4];
#pragma unroll
        for (int mi = 0; mi < 2; mi++)
#pragma unroll
            for (int ni = 0; ni < 4; ni++)
#pragma unroll
                for (int e = 0; e < 4; e++) acc[mi][ni][e] = 0.0f;

        warp_mma_f16<2, 4, 8>(acc, sb + E_A, sb + E_W2, m0, n0, lane);

        const float* b2s = (const float*)(smraw + E_B2);
#pragma unroll
        for (int mi = 0; mi < 2; mi++)
#pragma unroll
            for (int ni = 0; ni < 4; ni++) {
                int r = m0 + mi * 16 + (lane >> 2);
                int c = n0 + ni * 8 + 2 * (lane & 3);
                float bb0 = b2s[c], bb1 = b2s[c + 1];
                g_h2[((size_t)(b0 + r) * NA + a) * 32 + (c >> 1)] =
                    pack_h2(fmaxf(acc[mi][ni][0] + bb0, 0.0f),
                            fmaxf(acc[mi][ni][1] + bb1, 0.0f));
                g_h2[((size_t)(b0 + r + 8) * NA + a) * 32 + (c >> 1)] =
                    pack_h2(fmaxf(acc[mi][ni][2] + bb0, 0.0f),
                            fmaxf(acc[mi][ni][3] + bb1, 0.0f));
            }
    }
}

// ---------------------------------------------------------------------------
// k_comm via mma: comm[b] = (Mhi + Mlo) @ h[b]   (4 batch rows / block)
// A = M fp16 hi/lo (ldsm), B = h rows agent-major (ldsm.trans) -> tensor pipe
// ---------------------------------------------------------------------------
#define CM_MROW 80      // M image row stride (32 halfs + pad)
#define CM_HROW 144     // h image row stride (64 halfs + pad)
#define C_MH    0
#define C_ML    2560
#define C_H     5120    // + r*4608
#define C_SMEM  (5120 + 4 * 4608)   // 23552

__global__ __launch_bounds__(256) void k_comm() {
    __shared__ __align__(16) unsigned char csm[C_SMEM];
    const uint32_t sb = smem_u32(csm);
    const int tid  = threadIdx.x;
    const int w    = tid >> 5;
    const int lane = tid & 31;
    const int bbase = blockIdx.x * 4;

    // Stage M hi/lo images (rows stride 80B)
    {
        const uint4* ms = (const uint4*)g_m16;
        uint4 v = ms[tid];                       // 256 uint4 total
        int t = tid >> 7, row = (tid >> 2) & 31, q = tid & 3;
        *(uint4*)(csm + (t ? C_ML : C_MH) + row * CM_MROW + q * 16) = v;
    }
    // Stage h rows for 4 batches (rows stride 144B)
    {
        const uint4* hsrc = (const uint4*)g_h2;
        for (int i = tid; i < 1024; i += 256) {
            int r = i >> 8, j = (i >> 3) & 31, q = i & 7;
            uint4 v = hsrc[(((size_t)(bbase + r) * NA + j) << 3) + q];
            *(uint4*)(csm + C_H + r * 4608 + j * CM_HROW + q * 16) = v;
        }
    }
    __syncthreads();

    const int r  = w >> 1;       // batch row within block
    const int ih = w & 1;        // agent half: i 0-15 or 16-31
    const int b  = bbase + r;

    // A fragments (loop-invariant): [term][kstep][4]
    uint32_t A[2][2][4];
    const uint32_t aOffM = (uint32_t)((lane & 7) + ((lane >> 3) & 1) * 8) * CM_MROW
                         + (uint32_t)((lane >> 4) & 1) * 16;
#pragma unroll
    for (int t = 0; t < 2; t++)
#pragma unroll
        for (int ks = 0; ks < 2; ks++)
            ldsm_x4(A[t][ks][0], A[t][ks][1], A[t][ks][2], A[t][ks][3],
                    sb + (t ? C_ML : C_MH) + (uint32_t)(ih * 16) * CM_MROW
                       + (uint32_t)ks * 32 + aOffM);

    float acc[8][4];
#pragma unroll
    for (int nt = 0; nt < 8; nt++)
#pragma unroll
        for (int e = 0; e < 4; e++) acc[nt][e] = 0.0f;

    // B via ldsm.trans: rows = k (agent j), cols = n
    const uint32_t hb = sb + C_H + r * 4608;
    const uint32_t bOffT = (uint32_t)((lane & 7) + ((lane >> 3) & 1) * 8) * CM_HROW
                         + (uint32_t)((lane >> 4) & 1) * 16;
#pragma unroll
    for (int nj = 0; nj < 4; nj++) {
#pragma unroll
        for (int ks = 0; ks < 2; ks++) {
            uint32_t b0, b1, b2, b3;
            ldsm_x4_t(b0, b1, b2, b3,
                      hb + (uint32_t)(ks * 16) * CM_HROW + (uint32_t)nj * 32 + bOffT);
            uint32_t bf0[2] = {b0, b1};
            uint32_t bf1[2] = {b2, b3};
#pragma unroll
            for (int t = 0; t < 2; t++) {
                mma16816(acc[2 * nj],     A[t][ks], bf0);
                mma16816(acc[2 * nj + 1], A[t][ks], bf1);
            }
        }
    }

    // Epilogue: pack half2, write comm
#pragma unroll
    for (int nt = 0; nt < 8; nt++) {
        int i0 = ih * 16 + (lane >> 2);
        int n  = nt * 8 + 2 * (lane & 3);
        g_c2[((size_t)b * NA + i0) * 32 + (n >> 1)]     = pack_h2(acc[nt][0], acc[nt][1]);
        g_c2[((size_t)b * NA + i0 + 8) * 32 + (n >> 1)] = pack_h2(acc[nt][2], acc[nt][3]);
    }
}

// ---------------------------------------------------------------------------
// k_final: h2 = tanh([h,comm]@Wc + bc); q = h2@Wd + bd (both via mma)
// ---------------------------------------------------------------------------
#define F_A    0
#define F_WC   34816
#define F_WDT  52224
#define F_BC   56576
#define F_BD   56832
#define F_SMEM 56896

__global__ __launch_bounds__(256) void k_final(
    const float* __restrict__ bc, const float* __restrict__ bd,
    float* __restrict__ q)
{
    extern __shared__ unsigned char smraw[];
    const uint32_t sbm = smem_u32(smraw);
    const int tid  = threadIdx.x;
    const int w    = tid >> 5;
    const int lane = tid & 31;
    const int a    = blockIdx.y;
    const int b0   = blockIdx.x * 128;

    {
        const float4* s3 = (const float4*)(g_Wct + (size_t)a * 17408);
        float4* d3 = (float4*)(smraw + F_WC);
        for (int i = tid; i < 1088; i += 256) d3[i] = s3[i];
        const float4* s4 = (const float4*)(g_Wdt + (size_t)a * 4352);
        float4* d4 = (float4*)(smraw + F_WDT);
        for (int i = tid; i < 272; i += 256) d4[i] = s4[i];
    }
    for (int i = tid; i < 128 * 64; i += 256) {
        int m = i >> 6, j = i & 63;
        uint32_t v = (j < 32)
            ? g_h2[((size_t)(b0 + m) * NA + a) * 32 + j]
            : g_c2[((size_t)(b0 + m) * NA + a) * 32 + (j - 32)];
        sts_u32(sbm + F_A + (uint32_t)m * ROWB + (uint32_t)j * 4, v);
    }
    if (tid < NHX)  ((float*)(smraw + F_BC))[tid] = bc[a * NHX + tid];
    if (tid < NACT) ((float*)(smraw + F_BD))[tid] = bd[a * NACT + tid];
    __syncthreads();

    // GEMM3: pre[128,64] ; warp tile 32m x 32n
    {
        float acc[2][4][4];
#pragma unroll
        for (int mi = 0; mi < 2; mi++)
#pragma unroll
            for (int ni = 0; ni < 4; ni++)
#pragma unroll
                for (int e = 0; e < 4; e++) acc[mi][ni][e] = 0.0f;

        const int m0 = (w & 3) * 32;
        const int n0 = (w >> 2) * 32;
        warp_mma_f16<2, 4, 8>(acc, sbm + F_A, sbm + F_WC, m0, n0, lane);
        __syncthreads();

        const float* bcs = (const float*)(smraw + F_BC);
#pragma unroll
        for (int mi = 0; mi < 2; mi++)
#pragma unroll
            for (int ni = 0; ni < 4; ni++) {
                int r = m0 + mi * 16 + (lane >> 2);
                int c = n0 + ni * 8 + 2 * (lane & 3);
                float bb0 = bcs[c], bb1 = bcs[c + 1];
                uint32_t off = (uint32_t)r * ROWB + (uint32_t)c * 2;
                sts_u32(sbm + F_A + off,
                        pack_h2(tanhf(acc[mi][ni][0] + bb0), tanhf(acc[mi][ni][1] + bb1)));
                sts_u32(sbm + F_A + off + 8 * ROWB,
                        pack_h2(tanhf(acc[mi][ni][2] + bb0), tanhf(acc[mi][ni][3] + bb1)));
            }
    }
    __syncthreads();

    // GEMM4: q[128,16] ; warp w -> rows w*16..w*16+15, K=64
    {
        float acc[1][2][4];
#pragma unroll
        for (int ni = 0; ni < 2; ni++)
#pragma unroll
            for (int e = 0; e < 4; e++) acc[0][ni][e] = 0.0f;

        warp_mma_f16<1, 2, 4>(acc, sbm + F_A, sbm + F_WDT, w * 16, 0, lane);

        const float* bds = (const float*)(smraw + F_BD);
#pragma unroll
        for (int ni = 0; ni < 2; ni++) {
            int r = w * 16 + (lane >> 2);
            int c = ni * 8 + 2 * (lane & 3);
            float bb0 = bds[c], bb1 = bds[c + 1];
            *(float2*)(q + ((size_t)(b0 + r) * NA + a) * NACT + c) =
                make_float2(acc[0][ni][0] + bb0, acc[0][ni][1] + bb1);
            *(float2*)(q + ((size_t)(b0 + r + 8) * NA + a) * NACT + c) =
                make_float2(acc[0][ni][2] + bb0, acc[0][ni][3] + bb1);
        }
    }
}

// ---------------------------------------------------------------------------
extern "C" void kernel_launch(void* const* d_in, const int* in_sizes, int n_in,
                              void* d_out, int out_size) {
    const float* obs = (const float*)d_in[0];
    const float* W1  = (const float*)d_in[1];
    const float* b1  = (const float*)d_in[2];
    const float* W2  = (const float*)d_in[3];
    const float* b2  = (const float*)d_in[4];
    // d_in[5], d_in[6]: Wg, bg — dead code (gates never reach the output)
    const float* Wc  = (const float*)d_in[7];
    const float* bc  = (const float*)d_in[8];
    const float* Wd  = (const float*)d_in[9];
    const float* bd  = (const float*)d_in[10];
    const int*   cm  = (const int*)d_in[11];
    float* q = (float*)d_out;

    cudaFuncSetAttribute(k_encode, cudaFuncAttributeMaxDynamicSharedMemorySize, E_SMEM);
    cudaFuncSetAttribute(k_final,  cudaFuncAttributeMaxDynamicSharedMemorySize, F_SMEM);

    k_mask<<<1, 32>>>(cm);
    k_prep<<<256, 256>>>(W1, W2, Wc, Wd);
    k_encode<<<dim3(NB / 128, NA), 256, E_SMEM>>>(obs, b1, b2);
    k_comm<<<NB / 4, 256>>>();
    k_final<<<dim3(NB / 128, NA), 256, F_SMEM>>>(bc, bd, q);
}